// round 9
// baseline (speedup 1.0000x reference)
#include <cuda_runtime.h>
#include <cstdint>

// Graph unpooling: out[dst] += edge_attr * x[src]
//   x [50000,128] f32, src/dst [E=800000] i32, edge_attr [E] f32, out [200000,128] f32
// dst-CSR built per call: hist (atomic rank) -> warp-lookback scan -> atomic-free
// fill. Then warp-per-node shfl-broadcast gather, one streaming store.

#define MAXN   200704
#define MAXE   800000
#define SCAN_B 1024
#define NBLK_MAX 256

__device__ int  g_count[MAXN];     // per-node edge count
__device__ int2 g_meta[MAXN];      // {segment start, count}
__device__ int  g_rank[MAXE];      // edge rank within its dst segment
__device__ int2 g_edges[MAXE];     // CSR payload: {src, bitcast(weight)}

// decoupled-lookback state
__device__ int           g_ticket;
__device__ volatile int  g_flag[NBLK_MAX];     // 0=invalid 1=aggregate 2=prefix
__device__ volatile int  g_aggr[NBLK_MAX];
__device__ volatile int  g_pfx[NBLK_MAX];

__global__ void k_reset(int n, int nb) {
    int i = blockIdx.x * blockDim.x + threadIdx.x;
    if (i < n) g_count[i] = 0;
    if (i < nb) g_flag[i] = 0;
    if (i == 0) g_ticket = 0;
}

// One edge per thread; atomic return value = rank within dst segment.
__global__ void k_hist(const int* __restrict__ dst, int E) {
    int e = blockIdx.x * blockDim.x + threadIdx.x;
    if (e < E) g_rank[e] = atomicAdd(&g_count[dst[e]], 1);
}

// Single-pass scan, warp-parallel decoupled lookback (32 predecessors/round).
__global__ void __launch_bounds__(SCAN_B)
k_scan(int n) {
    __shared__ int swarp[32];
    __shared__ int sbid, sbase;
    int t = threadIdx.x, lane = t & 31, wid = t >> 5;

    if (t == 0) sbid = atomicAdd(&g_ticket, 1);
    __syncthreads();
    int bid = sbid;
    int i = bid * SCAN_B + t;
    int c = (i < n) ? g_count[i] : 0;

    int v = c;
    #pragma unroll
    for (int off = 1; off < 32; off <<= 1) {
        int u = __shfl_up_sync(0xffffffffu, v, off);
        if (lane >= off) v += u;
    }
    if (lane == 31) swarp[wid] = v;
    __syncthreads();
    if (wid == 0) {
        int w = swarp[lane];
        #pragma unroll
        for (int off = 1; off < 32; off <<= 1) {
            int u = __shfl_up_sync(0xffffffffu, w, off);
            if (lane >= off) w += u;
        }
        swarp[lane] = w;
    }
    __syncthreads();
    int incl  = v + (wid > 0 ? swarp[wid - 1] : 0);
    int total = swarp[31];

    if (wid == 0) {
        if (bid == 0) {
            if (lane == 0) {
                g_pfx[0] = total; __threadfence(); g_flag[0] = 2;
                sbase = 0;
            }
        } else {
            if (lane == 0) {
                g_aggr[bid] = total; __threadfence(); g_flag[bid] = 1;
            }
            int base = 0;
            for (int win = bid - 1; win >= 0; win -= 32) {
                int j = win - lane;            // lane 0 = nearest predecessor
                int f = 0, val = 0;
                if (j >= 0) {
                    while ((f = g_flag[j]) == 0) { }
                    val = (f == 2) ? g_pfx[j] : g_aggr[j];
                }
                unsigned pmask = __ballot_sync(0xffffffffu, (j >= 0) && (f == 2));
                int cut = pmask ? (__ffs(pmask) - 1) : 32;
                int contrib = (j >= 0 && lane <= cut) ? val : 0;
                #pragma unroll
                for (int off = 16; off; off >>= 1)
                    contrib += __shfl_down_sync(0xffffffffu, contrib, off);
                if (lane == 0) base += contrib;
                if (pmask) break;
            }
            if (lane == 0) {
                g_pfx[bid] = base + total; __threadfence(); g_flag[bid] = 2;
                sbase = base;
            }
        }
    }
    __syncthreads();

    if (i < n) g_meta[i] = make_int2(sbase + incl - c, c);
}

// Atomic-free fill: pos = segment_start + precomputed rank.
__global__ void k_fill(const int* __restrict__ src, const int* __restrict__ dst,
                       const float* __restrict__ attr, int E) {
    int e = blockIdx.x * blockDim.x + threadIdx.x;
    if (e >= E) return;
    int d   = __ldg(&dst[e]);
    int st  = __ldg(&((const int*)g_meta)[2 * d]);     // g_meta[d].x
    int pos = st + __ldg(&g_rank[e]);
    g_edges[pos] = make_int2(__ldg(&src[e]), __float_as_int(__ldg(&attr[e])));
}

// One warp per fine node. Lanes cooperatively load up to 32 edge records in one
// round, broadcast via shfl (x-load addresses ready instantly), then 4-deep
// pipelined row loads with 4 accumulators. Single streaming store.
__global__ void __launch_bounds__(256)
k_gather(const float4* __restrict__ x4, float4* __restrict__ out4, int n) {
    int gtid = blockIdx.x * blockDim.x + threadIdx.x;
    int node = gtid >> 5;
    int lane = gtid & 31;
    if (node >= n) return;

    int2 mc  = __ldg(&g_meta[node]);
    int  beg = mc.x, cnt = mc.y;

    float4 a0 = make_float4(0.f, 0.f, 0.f, 0.f);
    float4 a1 = make_float4(0.f, 0.f, 0.f, 0.f);
    float4 a2 = make_float4(0.f, 0.f, 0.f, 0.f);
    float4 a3 = make_float4(0.f, 0.f, 0.f, 0.f);

    for (int base = 0; base < cnt; base += 32) {
        int rem = cnt - base; if (rem > 32) rem = 32;
        int2 my = (lane < rem) ? __ldg(&g_edges[beg + base + lane])
                               : make_int2(0, 0);
        int k = 0;
        for (; k + 3 < rem; k += 4) {
            int s0 = __shfl_sync(0xffffffffu, my.x, k);
            int s1 = __shfl_sync(0xffffffffu, my.x, k + 1);
            int s2 = __shfl_sync(0xffffffffu, my.x, k + 2);
            int s3 = __shfl_sync(0xffffffffu, my.x, k + 3);
            float w0 = __int_as_float(__shfl_sync(0xffffffffu, my.y, k));
            float w1 = __int_as_float(__shfl_sync(0xffffffffu, my.y, k + 1));
            float w2 = __int_as_float(__shfl_sync(0xffffffffu, my.y, k + 2));
            float w3 = __int_as_float(__shfl_sync(0xffffffffu, my.y, k + 3));
            float4 v0 = __ldg(&x4[(size_t)s0 * 32 + lane]);
            float4 v1 = __ldg(&x4[(size_t)s1 * 32 + lane]);
            float4 v2 = __ldg(&x4[(size_t)s2 * 32 + lane]);
            float4 v3 = __ldg(&x4[(size_t)s3 * 32 + lane]);
            a0.x += w0 * v0.x; a0.y += w0 * v0.y; a0.z += w0 * v0.z; a0.w += w0 * v0.w;
            a1.x += w1 * v1.x; a1.y += w1 * v1.y; a1.z += w1 * v1.z; a1.w += w1 * v1.w;
            a2.x += w2 * v2.x; a2.y += w2 * v2.y; a2.z += w2 * v2.z; a2.w += w2 * v2.w;
            a3.x += w3 * v3.x; a3.y += w3 * v3.y; a3.z += w3 * v3.z; a3.w += w3 * v3.w;
        }
        if (k + 1 < rem) {
            int s0 = __shfl_sync(0xffffffffu, my.x, k);
            int s1 = __shfl_sync(0xffffffffu, my.x, k + 1);
            float w0 = __int_as_float(__shfl_sync(0xffffffffu, my.y, k));
            float w1 = __int_as_float(__shfl_sync(0xffffffffu, my.y, k + 1));
            float4 v0 = __ldg(&x4[(size_t)s0 * 32 + lane]);
            float4 v1 = __ldg(&x4[(size_t)s1 * 32 + lane]);
            a0.x += w0 * v0.x; a0.y += w0 * v0.y; a0.z += w0 * v0.z; a0.w += w0 * v0.w;
            a1.x += w1 * v1.x; a1.y += w1 * v1.y; a1.z += w1 * v1.z; a1.w += w1 * v1.w;
            k += 2;
        }
        if (k < rem) {
            int s0 = __shfl_sync(0xffffffffu, my.x, k);
            float w0 = __int_as_float(__shfl_sync(0xffffffffu, my.y, k));
            float4 v0 = __ldg(&x4[(size_t)s0 * 32 + lane]);
            a0.x += w0 * v0.x; a0.y += w0 * v0.y; a0.z += w0 * v0.z; a0.w += w0 * v0.w;
        }
    }
    a0.x += a1.x; a0.y += a1.y; a0.z += a1.z; a0.w += a1.w;
    a2.x += a3.x; a2.y += a3.y; a2.z += a3.z; a2.w += a3.w;
    a0.x += a2.x; a0.y += a2.y; a0.z += a2.z; a0.w += a2.w;
    __stcs(&out4[(size_t)node * 32 + lane], a0);
}

extern "C" void kernel_launch(void* const* d_in, const int* in_sizes, int n_in,
                              void* d_out, int out_size) {
    const float4* x4   = (const float4*)d_in[0];
    const int*    src  = (const int*)d_in[1];
    const int*    dst  = (const int*)d_in[2];
    const float*  attr = (const float*)d_in[3];
    float4*       out4 = (float4*)d_out;

    int E  = in_sizes[1];
    int n  = out_size / 128;                 // fine nodes (C=128)
    int nb = (n + SCAN_B - 1) / SCAN_B;      // scan blocks (<= NBLK_MAX)

    int tb = 256;
    k_reset<<<(n + tb - 1) / tb, tb>>>(n, nb);
    k_hist <<<(E + tb - 1) / tb, tb>>>(dst, E);
    k_scan <<<nb, SCAN_B>>>(n);
    k_fill <<<(E + tb - 1) / tb, tb>>>(src, dst, attr, E);

    long long gt = (long long)n * 32;
    k_gather<<<(int)((gt + tb - 1) / tb), tb>>>(x4, out4, n);
}

// round 10
// speedup vs baseline: 1.0578x; 1.0578x over previous
#include <cuda_runtime.h>
#include <cstdint>

// Graph unpooling: out[dst] += edge_attr * x[src]
//   x [50000,128] f32, src/dst [E=800000] i32, edge_attr [E] f32, out [200000,128] f32
// dst-CSR built per call: hist (atomic rank) -> warp-lookback scan -> atomic-free
// fill. Then warp-per-node 2-deep gather, one streaming store.

#define MAXN   200704
#define MAXE   800000
#define SCAN_B 1024
#define NBLK_MAX 256

__device__ int  g_count[MAXN];     // per-node edge count
__device__ int2 g_meta[MAXN];      // {segment start, count}
__device__ int  g_rank[MAXE];      // edge rank within its dst segment
__device__ int2 g_edges[MAXE];     // CSR payload: {src, bitcast(weight)}

// decoupled-lookback state
__device__ int           g_ticket;
__device__ volatile int  g_flag[NBLK_MAX];     // 0=invalid 1=aggregate 2=prefix
__device__ volatile int  g_aggr[NBLK_MAX];
__device__ volatile int  g_pfx[NBLK_MAX];

__global__ void k_reset(int n, int nb) {
    int i = blockIdx.x * blockDim.x + threadIdx.x;
    if (i < n) g_count[i] = 0;
    if (i < nb) g_flag[i] = 0;
    if (i == 0) g_ticket = 0;
}

// One edge per thread; atomic return value = rank within dst segment.
__global__ void k_hist(const int* __restrict__ dst, int E) {
    int e = blockIdx.x * blockDim.x + threadIdx.x;
    if (e < E) {
        int r = atomicAdd(&g_count[__ldg(&dst[e])], 1);
        __stcs(&g_rank[e], r);         // streaming: written once, read once
    }
}

// Single-pass scan, warp-parallel decoupled lookback (32 predecessors/round).
__global__ void __launch_bounds__(SCAN_B)
k_scan(int n) {
    __shared__ int swarp[32];
    __shared__ int sbid, sbase;
    int t = threadIdx.x, lane = t & 31, wid = t >> 5;

    if (t == 0) sbid = atomicAdd(&g_ticket, 1);
    __syncthreads();
    int bid = sbid;
    int i = bid * SCAN_B + t;
    int c = (i < n) ? g_count[i] : 0;

    int v = c;
    #pragma unroll
    for (int off = 1; off < 32; off <<= 1) {
        int u = __shfl_up_sync(0xffffffffu, v, off);
        if (lane >= off) v += u;
    }
    if (lane == 31) swarp[wid] = v;
    __syncthreads();
    if (wid == 0) {
        int w = swarp[lane];
        #pragma unroll
        for (int off = 1; off < 32; off <<= 1) {
            int u = __shfl_up_sync(0xffffffffu, w, off);
            if (lane >= off) w += u;
        }
        swarp[lane] = w;
    }
    __syncthreads();
    int incl  = v + (wid > 0 ? swarp[wid - 1] : 0);
    int total = swarp[31];

    if (wid == 0) {
        if (bid == 0) {
            if (lane == 0) {
                g_pfx[0] = total; __threadfence(); g_flag[0] = 2;
                sbase = 0;
            }
        } else {
            if (lane == 0) {
                g_aggr[bid] = total; __threadfence(); g_flag[bid] = 1;
            }
            int base = 0;
            for (int win = bid - 1; win >= 0; win -= 32) {
                int j = win - lane;            // lane 0 = nearest predecessor
                int f = 0, val = 0;
                if (j >= 0) {
                    while ((f = g_flag[j]) == 0) { }
                    val = (f == 2) ? g_pfx[j] : g_aggr[j];
                }
                unsigned pmask = __ballot_sync(0xffffffffu, (j >= 0) && (f == 2));
                int cut = pmask ? (__ffs(pmask) - 1) : 32;
                int contrib = (j >= 0 && lane <= cut) ? val : 0;
                #pragma unroll
                for (int off = 16; off; off >>= 1)
                    contrib += __shfl_down_sync(0xffffffffu, contrib, off);
                if (lane == 0) base += contrib;
                if (pmask) break;
            }
            if (lane == 0) {
                g_pfx[bid] = base + total; __threadfence(); g_flag[bid] = 2;
                sbase = base;
            }
        }
    }
    __syncthreads();

    if (i < n) g_meta[i] = make_int2(sbase + incl - c, c);
}

// Atomic-free fill: pos = segment_start + precomputed rank.
__global__ void k_fill(const int* __restrict__ src, const int* __restrict__ dst,
                       const float* __restrict__ attr, int E) {
    int e = blockIdx.x * blockDim.x + threadIdx.x;
    if (e >= E) return;
    int d   = __ldg(&dst[e]);
    int st  = __ldg(&((const int*)g_meta)[2 * d]);     // g_meta[d].x
    int pos = st + __ldg(&g_rank[e]);
    g_edges[pos] = make_int2(__ldg(&src[e]), __float_as_int(__ldg(&attr[e])));
}

// One warp per fine node: 2-deep load pipeline (matches avg fan-in 4),
// register accumulate, single streaming store (keeps x resident in L2).
__global__ void __launch_bounds__(256)
k_gather(const float4* __restrict__ x4, float4* __restrict__ out4, int n) {
    int gtid = blockIdx.x * blockDim.x + threadIdx.x;
    int node = gtid >> 5;
    int lane = gtid & 31;
    if (node >= n) return;

    int2 mc  = __ldg(&g_meta[node]);
    int  beg = mc.x, cnt = mc.y;

    float4 acc = make_float4(0.f, 0.f, 0.f, 0.f);
    int k = 0;
    for (; k + 1 < cnt; k += 2) {
        int2 e0 = __ldg(&g_edges[beg + k]);
        int2 e1 = __ldg(&g_edges[beg + k + 1]);
        float4 v0 = __ldg(&x4[(size_t)e0.x * 32 + lane]);
        float4 v1 = __ldg(&x4[(size_t)e1.x * 32 + lane]);
        float w0 = __int_as_float(e0.y);
        float w1 = __int_as_float(e1.y);
        acc.x += w0 * v0.x; acc.y += w0 * v0.y; acc.z += w0 * v0.z; acc.w += w0 * v0.w;
        acc.x += w1 * v1.x; acc.y += w1 * v1.y; acc.z += w1 * v1.z; acc.w += w1 * v1.w;
    }
    if (k < cnt) {
        int2 e0 = __ldg(&g_edges[beg + k]);
        float4 v0 = __ldg(&x4[(size_t)e0.x * 32 + lane]);
        float w0 = __int_as_float(e0.y);
        acc.x += w0 * v0.x; acc.y += w0 * v0.y; acc.z += w0 * v0.z; acc.w += w0 * v0.w;
    }
    __stcs(&out4[(size_t)node * 32 + lane], acc);
}

extern "C" void kernel_launch(void* const* d_in, const int* in_sizes, int n_in,
                              void* d_out, int out_size) {
    const float4* x4   = (const float4*)d_in[0];
    const int*    src  = (const int*)d_in[1];
    const int*    dst  = (const int*)d_in[2];
    const float*  attr = (const float*)d_in[3];
    float4*       out4 = (float4*)d_out;

    int E  = in_sizes[1];
    int n  = out_size / 128;                 // fine nodes (C=128)
    int nb = (n + SCAN_B - 1) / SCAN_B;      // scan blocks (<= NBLK_MAX)

    int tb = 256;
    k_reset<<<(n + tb - 1) / tb, tb>>>(n, nb);
    k_hist <<<(E + tb - 1) / tb, tb>>>(dst, E);
    k_scan <<<nb, SCAN_B>>>(n);
    k_fill <<<(E + tb - 1) / tb, tb>>>(src, dst, attr, E);

    long long gt = (long long)n * 32;
    k_gather<<<(int)((gt + tb - 1) / tb), tb>>>(x4, out4, n);
}

// round 11
// speedup vs baseline: 1.0838x; 1.0245x over previous
#include <cuda_runtime.h>
#include <cstdint>

// Graph unpooling: out[dst] += edge_attr * x[src]
//   x [50000,128] f32, src/dst [E=800000] i32, edge_attr [E] f32, out [200000,128] f32
// dst-CSR built per call: hist (atomic rank) -> warp-lookback scan -> atomic-free
// fill. Gather: warp-per-node, predicated 4-burst + 2-deep remainder loop,
// one streaming store.

#define MAXN   200704
#define MAXE   800000
#define SCAN_B 1024
#define NBLK_MAX 256

__device__ int  g_count[MAXN];     // per-node edge count
__device__ int2 g_meta[MAXN];      // {segment start, count}
__device__ int  g_rank[MAXE];      // edge rank within its dst segment
__device__ int2 g_edges[MAXE];     // CSR payload: {src, bitcast(weight)}

// decoupled-lookback state
__device__ int           g_ticket;
__device__ volatile int  g_flag[NBLK_MAX];     // 0=invalid 1=aggregate 2=prefix
__device__ volatile int  g_aggr[NBLK_MAX];
__device__ volatile int  g_pfx[NBLK_MAX];

__global__ void k_reset(int n, int nb) {
    int i = blockIdx.x * blockDim.x + threadIdx.x;
    if (i < n) g_count[i] = 0;
    if (i < nb) g_flag[i] = 0;
    if (i == 0) g_ticket = 0;
}

// One edge per thread; atomic return value = rank within dst segment.
__global__ void k_hist(const int* __restrict__ dst, int E) {
    int e = blockIdx.x * blockDim.x + threadIdx.x;
    if (e < E) {
        int r = atomicAdd(&g_count[__ldg(&dst[e])], 1);
        __stcs(&g_rank[e], r);
    }
}

// Single-pass scan, warp-parallel decoupled lookback (32 predecessors/round).
__global__ void __launch_bounds__(SCAN_B)
k_scan(int n) {
    __shared__ int swarp[32];
    __shared__ int sbid, sbase;
    int t = threadIdx.x, lane = t & 31, wid = t >> 5;

    if (t == 0) sbid = atomicAdd(&g_ticket, 1);
    __syncthreads();
    int bid = sbid;
    int i = bid * SCAN_B + t;
    int c = (i < n) ? g_count[i] : 0;

    int v = c;
    #pragma unroll
    for (int off = 1; off < 32; off <<= 1) {
        int u = __shfl_up_sync(0xffffffffu, v, off);
        if (lane >= off) v += u;
    }
    if (lane == 31) swarp[wid] = v;
    __syncthreads();
    if (wid == 0) {
        int w = swarp[lane];
        #pragma unroll
        for (int off = 1; off < 32; off <<= 1) {
            int u = __shfl_up_sync(0xffffffffu, w, off);
            if (lane >= off) w += u;
        }
        swarp[lane] = w;
    }
    __syncthreads();
    int incl  = v + (wid > 0 ? swarp[wid - 1] : 0);
    int total = swarp[31];

    if (wid == 0) {
        if (bid == 0) {
            if (lane == 0) {
                g_pfx[0] = total; __threadfence(); g_flag[0] = 2;
                sbase = 0;
            }
        } else {
            if (lane == 0) {
                g_aggr[bid] = total; __threadfence(); g_flag[bid] = 1;
            }
            int base = 0;
            for (int win = bid - 1; win >= 0; win -= 32) {
                int j = win - lane;
                int f = 0, val = 0;
                if (j >= 0) {
                    while ((f = g_flag[j]) == 0) { }
                    val = (f == 2) ? g_pfx[j] : g_aggr[j];
                }
                unsigned pmask = __ballot_sync(0xffffffffu, (j >= 0) && (f == 2));
                int cut = pmask ? (__ffs(pmask) - 1) : 32;
                int contrib = (j >= 0 && lane <= cut) ? val : 0;
                #pragma unroll
                for (int off = 16; off; off >>= 1)
                    contrib += __shfl_down_sync(0xffffffffu, contrib, off);
                if (lane == 0) base += contrib;
                if (pmask) break;
            }
            if (lane == 0) {
                g_pfx[bid] = base + total; __threadfence(); g_flag[bid] = 2;
                sbase = base;
            }
        }
    }
    __syncthreads();

    if (i < n) g_meta[i] = make_int2(sbase + incl - c, c);
}

// Atomic-free fill: pos = segment_start + precomputed rank.
__global__ void k_fill(const int* __restrict__ src, const int* __restrict__ dst,
                       const float* __restrict__ attr, int E) {
    int e = blockIdx.x * blockDim.x + threadIdx.x;
    if (e >= E) return;
    int d   = __ldg(&dst[e]);
    int st  = __ldg(&((const int*)g_meta)[2 * d]);     // g_meta[d].x
    int pos = st + __ldg(&g_rank[e]);
    g_edges[pos] = make_int2(__ldg(&src[e]), __float_as_int(__ldg(&attr[e])));
}

// One warp per fine node. Predicated straight-line burst of up to 4 edges
// (covers 63% of nodes in one 2-stage latency chain), then 2-deep loop for
// the rest. Predicated-off loads issue nothing (no extra traffic).
__global__ void __launch_bounds__(256)
k_gather(const float4* __restrict__ x4, float4* __restrict__ out4, int n) {
    int gtid = blockIdx.x * blockDim.x + threadIdx.x;
    int node = gtid >> 5;
    int lane = gtid & 31;
    if (node >= n) return;

    int2 mc  = __ldg(&g_meta[node]);
    int  beg = mc.x, cnt = mc.y;

    const float4 fz = make_float4(0.f, 0.f, 0.f, 0.f);
    float4 a0 = fz, a1 = fz;

    // burst: predicated loads, all independent, issue back-to-back
    int2 e0 = make_int2(0, 0), e1 = e0, e2 = e0, e3 = e0;
    if (cnt > 0) e0 = __ldg(&g_edges[beg]);
    if (cnt > 1) e1 = __ldg(&g_edges[beg + 1]);
    if (cnt > 2) e2 = __ldg(&g_edges[beg + 2]);
    if (cnt > 3) e3 = __ldg(&g_edges[beg + 3]);
    float4 v0 = fz, v1 = fz, v2 = fz, v3 = fz;
    if (cnt > 0) v0 = __ldg(&x4[(size_t)e0.x * 32 + lane]);
    if (cnt > 1) v1 = __ldg(&x4[(size_t)e1.x * 32 + lane]);
    if (cnt > 2) v2 = __ldg(&x4[(size_t)e2.x * 32 + lane]);
    if (cnt > 3) v3 = __ldg(&x4[(size_t)e3.x * 32 + lane]);
    {
        float w0 = __int_as_float(e0.y), w1 = __int_as_float(e1.y);
        float w2 = __int_as_float(e2.y), w3 = __int_as_float(e3.y);
        a0.x += w0 * v0.x; a0.y += w0 * v0.y; a0.z += w0 * v0.z; a0.w += w0 * v0.w;
        a1.x += w1 * v1.x; a1.y += w1 * v1.y; a1.z += w1 * v1.z; a1.w += w1 * v1.w;
        a0.x += w2 * v2.x; a0.y += w2 * v2.y; a0.z += w2 * v2.z; a0.w += w2 * v2.w;
        a1.x += w3 * v3.x; a1.y += w3 * v3.y; a1.z += w3 * v3.z; a1.w += w3 * v3.w;
    }

    // remainder: proven 2-deep pipeline
    int k = 4;
    for (; k + 1 < cnt; k += 2) {
        int2 f0 = __ldg(&g_edges[beg + k]);
        int2 f1 = __ldg(&g_edges[beg + k + 1]);
        float4 u0 = __ldg(&x4[(size_t)f0.x * 32 + lane]);
        float4 u1 = __ldg(&x4[(size_t)f1.x * 32 + lane]);
        float w0 = __int_as_float(f0.y);
        float w1 = __int_as_float(f1.y);
        a0.x += w0 * u0.x; a0.y += w0 * u0.y; a0.z += w0 * u0.z; a0.w += w0 * u0.w;
        a1.x += w1 * u1.x; a1.y += w1 * u1.y; a1.z += w1 * u1.z; a1.w += w1 * u1.w;
    }
    if (k < cnt) {
        int2 f0 = __ldg(&g_edges[beg + k]);
        float4 u0 = __ldg(&x4[(size_t)f0.x * 32 + lane]);
        float w0 = __int_as_float(f0.y);
        a0.x += w0 * u0.x; a0.y += w0 * u0.y; a0.z += w0 * u0.z; a0.w += w0 * u0.w;
    }

    a0.x += a1.x; a0.y += a1.y; a0.z += a1.z; a0.w += a1.w;
    __stcs(&out4[(size_t)node * 32 + lane], a0);
}

extern "C" void kernel_launch(void* const* d_in, const int* in_sizes, int n_in,
                              void* d_out, int out_size) {
    const float4* x4   = (const float4*)d_in[0];
    const int*    src  = (const int*)d_in[1];
    const int*    dst  = (const int*)d_in[2];
    const float*  attr = (const float*)d_in[3];
    float4*       out4 = (float4*)d_out;

    int E  = in_sizes[1];
    int n  = out_size / 128;                 // fine nodes (C=128)
    int nb = (n + SCAN_B - 1) / SCAN_B;      // scan blocks (<= NBLK_MAX)

    int tb = 256;
    k_reset<<<(n + tb - 1) / tb, tb>>>(n, nb);
    k_hist <<<(E + tb - 1) / tb, tb>>>(dst, E);
    k_scan <<<nb, SCAN_B>>>(n);
    k_fill <<<(E + tb - 1) / tb, tb>>>(src, dst, attr, E);

    long long gt = (long long)n * 32;
    k_gather<<<(int)((gt + tb - 1) / tb), tb>>>(x4, out4, n);
}

// round 12
// speedup vs baseline: 1.4167x; 1.3072x over previous
#include <cuda_runtime.h>
#include <cstdint>

// Graph unpooling: out[dst] += edge_attr * x[src]
//   x [50000,128] f32, src/dst [E=800000] i32, edge_attr [E] f32, out [200000,128] f32
// Fixed-capacity binning: 8 slots per fine node (covers ~98% of Poisson(4)
// fan-in), overflow to a list. bin -> gather(slots) -> spill(red.add).

#define MAXN   200704
#define MAXE   800000
#define CAP    8

__device__ int  g_count[MAXN];         // per-node edge count (may exceed CAP)
__device__ int2 g_slots[MAXN * CAP];   // {src, bitcast(weight)} per slot
__device__ int  g_ovf_n;               // overflow counter
__device__ int4 g_ovf[MAXE];           // overflow: {src, dst, w_bits, pad}

__global__ void k_reset(int n) {
    int i = blockIdx.x * blockDim.x + threadIdx.x;
    if (i < n) g_count[i] = 0;
    if (i == 0) g_ovf_n = 0;
}

// Fused hist+fill: bin each edge into its node's slot array (or overflow).
__global__ void k_bin(const int* __restrict__ src, const int* __restrict__ dst,
                      const float* __restrict__ attr, int E) {
    int e = blockIdx.x * blockDim.x + threadIdx.x;
    if (e >= E) return;
    int d = __ldg(&dst[e]);
    int s = __ldg(&src[e]);
    int w = __float_as_int(__ldg(&attr[e]));
    int r = atomicAdd(&g_count[d], 1);
    if (r < CAP) {
        g_slots[d * CAP + r] = make_int2(s, w);
    } else {
        int p = atomicAdd(&g_ovf_n, 1);
        g_ovf[p] = make_int4(s, d, w, 0);
    }
}

// One warp per fine node: predicated 4-burst x2 over the 8 fixed slots,
// register accumulate, single streaming store (keeps x resident in L2).
__global__ void __launch_bounds__(256)
k_gather(const float4* __restrict__ x4, float4* __restrict__ out4, int n) {
    int gtid = blockIdx.x * blockDim.x + threadIdx.x;
    int node = gtid >> 5;
    int lane = gtid & 31;
    if (node >= n) return;

    int cnt = __ldg(&g_count[node]);
    if (cnt > CAP) cnt = CAP;
    int beg = node * CAP;

    const float4 fz = make_float4(0.f, 0.f, 0.f, 0.f);
    float4 a0 = fz, a1 = fz;

    // burst 1: slots 0..3 (covers 63% of nodes entirely)
    int2 e0 = make_int2(0, 0), e1 = e0, e2 = e0, e3 = e0;
    if (cnt > 0) e0 = __ldg(&g_slots[beg]);
    if (cnt > 1) e1 = __ldg(&g_slots[beg + 1]);
    if (cnt > 2) e2 = __ldg(&g_slots[beg + 2]);
    if (cnt > 3) e3 = __ldg(&g_slots[beg + 3]);
    float4 v0 = fz, v1 = fz, v2 = fz, v3 = fz;
    if (cnt > 0) v0 = __ldg(&x4[(size_t)e0.x * 32 + lane]);
    if (cnt > 1) v1 = __ldg(&x4[(size_t)e1.x * 32 + lane]);
    if (cnt > 2) v2 = __ldg(&x4[(size_t)e2.x * 32 + lane]);
    if (cnt > 3) v3 = __ldg(&x4[(size_t)e3.x * 32 + lane]);
    {
        float w0 = __int_as_float(e0.y), w1 = __int_as_float(e1.y);
        float w2 = __int_as_float(e2.y), w3 = __int_as_float(e3.y);
        a0.x += w0 * v0.x; a0.y += w0 * v0.y; a0.z += w0 * v0.z; a0.w += w0 * v0.w;
        a1.x += w1 * v1.x; a1.y += w1 * v1.y; a1.z += w1 * v1.z; a1.w += w1 * v1.w;
        a0.x += w2 * v2.x; a0.y += w2 * v2.y; a0.z += w2 * v2.z; a0.w += w2 * v2.w;
        a1.x += w3 * v3.x; a1.y += w3 * v3.y; a1.z += w3 * v3.z; a1.w += w3 * v3.w;
    }

    // burst 2: slots 4..7 (predicated; rare)
    if (cnt > 4) {
        int2 f0 = __ldg(&g_slots[beg + 4]);
        int2 f1 = make_int2(0, 0), f2 = f1, f3 = f1;
        if (cnt > 5) f1 = __ldg(&g_slots[beg + 5]);
        if (cnt > 6) f2 = __ldg(&g_slots[beg + 6]);
        if (cnt > 7) f3 = __ldg(&g_slots[beg + 7]);
        float4 u0 = __ldg(&x4[(size_t)f0.x * 32 + lane]);
        float4 u1 = fz, u2 = fz, u3 = fz;
        if (cnt > 5) u1 = __ldg(&x4[(size_t)f1.x * 32 + lane]);
        if (cnt > 6) u2 = __ldg(&x4[(size_t)f2.x * 32 + lane]);
        if (cnt > 7) u3 = __ldg(&x4[(size_t)f3.x * 32 + lane]);
        float w0 = __int_as_float(f0.y), w1 = __int_as_float(f1.y);
        float w2 = __int_as_float(f2.y), w3 = __int_as_float(f3.y);
        a0.x += w0 * u0.x; a0.y += w0 * u0.y; a0.z += w0 * u0.z; a0.w += w0 * u0.w;
        a1.x += w1 * u1.x; a1.y += w1 * u1.y; a1.z += w1 * u1.z; a1.w += w1 * u1.w;
        a0.x += w2 * u2.x; a0.y += w2 * u2.y; a0.z += w2 * u2.z; a0.w += w2 * u2.w;
        a1.x += w3 * u3.x; a1.y += w3 * u3.y; a1.z += w3 * u3.z; a1.w += w3 * u3.w;
    }

    a0.x += a1.x; a0.y += a1.y; a0.z += a1.z; a0.w += a1.w;
    __stcs(&out4[(size_t)node * 32 + lane], a0);
}

// Overflow edges: warp per entry, red.add.v4 into out (runs after gather).
// Fixed grid; warps stride over the dynamic overflow count.
__global__ void __launch_bounds__(256)
k_spill(const float4* __restrict__ x4, float* __restrict__ out, int total_warps) {
    int gtid = blockIdx.x * blockDim.x + threadIdx.x;
    int warp = gtid >> 5;
    int lane = gtid & 31;
    int m = g_ovf_n;
    for (int i = warp; i < m; i += total_warps) {
        int4 e = g_ovf[i];
        float w = __int_as_float(e.z);
        float4 v = __ldg(&x4[(size_t)e.x * 32 + lane]);
        v.x *= w; v.y *= w; v.z *= w; v.w *= w;
        float* p = out + (size_t)e.y * 128 + (lane << 2);
        asm volatile("red.global.add.v4.f32 [%0], {%1, %2, %3, %4};"
                     :: "l"(p), "f"(v.x), "f"(v.y), "f"(v.z), "f"(v.w)
                     : "memory");
    }
}

extern "C" void kernel_launch(void* const* d_in, const int* in_sizes, int n_in,
                              void* d_out, int out_size) {
    const float4* x4   = (const float4*)d_in[0];
    const int*    src  = (const int*)d_in[1];
    const int*    dst  = (const int*)d_in[2];
    const float*  attr = (const float*)d_in[3];
    float4*       out4 = (float4*)d_out;

    int E = in_sizes[1];
    int n = out_size / 128;                  // fine nodes (C=128)

    int tb = 256;
    k_reset<<<(n + tb - 1) / tb, tb>>>(n);
    k_bin  <<<(E + tb - 1) / tb, tb>>>(src, dst, attr, E);

    long long gt = (long long)n * 32;
    k_gather<<<(int)((gt + tb - 1) / tb), tb>>>(x4, out4, n);

    int spill_blocks = 1184;                 // 8 blocks/SM, fixed grid
    k_spill<<<spill_blocks, tb>>>(x4, (float*)d_out, spill_blocks * 8);
}